// round 7
// baseline (speedup 1.0000x reference)
#include <cuda_runtime.h>
#include <cuda_bf16.h>
#include <cstdint>

// LogitSeparator: for each (b,d) row, copy logits[b, start:start+len] to the
// front of out[b,d,:], zero the rest; mask = 1.0 for the first len entries.
// start = exclusive cumsum of schemas[b,:] over D; len = schemas[b,d].
// Output buffer = concat(out, mask) as float32.
//
// NOTE: reference requests int64 schemas but JAX x64 is disabled by default,
// so the buffer is almost certainly int32. We detect the width on-device.

#define MAX_ROWS 65536
__device__ int g_start[MAX_ROWS];
__device__ int g_len[MAX_ROWS];

// One-block setup: detect schema element width, compute per-row start/len.
__global__ void setup_rows(const void* __restrict__ schemas_raw,
                           int B, int D, int L, int S0 /* = B*D */) {
    __shared__ int s_is64;  // 1 if buffer is int64, 0 if int32
    const int tid = threadIdx.x;

    if (tid == 0) s_is64 = 1;
    __syncthreads();

    // If dtype is int64 (values < 2^32), every odd int32 word is 0.
    // If dtype is int32, odd words are schema values (~0 prob all zero).
    const int* w = (const int*)schemas_raw;
    int any_odd_nonzero = 0;
    for (int i = 1 + 2 * tid; i < S0; i += 2 * blockDim.x)
        if (w[i] != 0) any_odd_nonzero = 1;
    if (any_odd_nonzero) atomicExch(&s_is64, 0);
    __syncthreads();
    const int is64 = s_is64;

    const long long* s64 = (const long long*)schemas_raw;
    const int*       s32 = (const int*)schemas_raw;

    for (int b = tid; b < B; b += blockDim.x) {
        long long cum = 0;
        for (int d = 0; d < D; ++d) {
            long long v = is64 ? s64[(long long)b * D + d]
                               : (long long)s32[(long long)b * D + d];
            long long st = cum;
            long long en = cum + v;
            cum = en;
            // clamp zone to [0, L)
            long long zs = st < L ? st : L;
            long long ze = en < L ? en : L;
            long long le = ze - zs; if (le < 0) le = 0;
            g_start[b * D + d] = (int)zs;
            g_len[b * D + d]   = (int)le;
        }
    }
}

__global__ void __launch_bounds__(256)
logit_sep_vec4(const float* __restrict__ logits,
               float* __restrict__ out,
               float* __restrict__ mout,   // may be null
               int D, int L) {
    const int row = blockIdx.x;          // b*D + d
    const int b = row / D;

    const int start = g_start[row];
    const int len   = g_len[row];

    const size_t base = (size_t)row * (size_t)L;
    float4* __restrict__ orow = (float4*)(out + base);
    float4* __restrict__ mrow = mout ? (float4*)(mout + base) : nullptr;
    const float* __restrict__ lrow = logits + (size_t)b * L + start;

    const int nvec = L >> 2;
    const float4 z4   = make_float4(0.f, 0.f, 0.f, 0.f);
    const float4 one4 = make_float4(1.f, 1.f, 1.f, 1.f);

    for (int v = threadIdx.x; v < nvec; v += blockDim.x) {
        const int j = v << 2;
        if (j >= len) {
            // dominant path: streaming zero stores, back-to-back
            __stcs(&orow[v], z4);
            if (mrow) __stcs(&mrow[v], z4);
        } else if (j + 3 < len) {
            float4 o = make_float4(lrow[j], lrow[j + 1], lrow[j + 2], lrow[j + 3]);
            __stcs(&orow[v], o);
            if (mrow) __stcs(&mrow[v], one4);
        } else {
            // boundary vector (at most one per row)
            float4 o, m;
            o.x = (j + 0 < len) ? lrow[j + 0] : 0.f;  m.x = (j + 0 < len) ? 1.f : 0.f;
            o.y = (j + 1 < len) ? lrow[j + 1] : 0.f;  m.y = (j + 1 < len) ? 1.f : 0.f;
            o.z = (j + 2 < len) ? lrow[j + 2] : 0.f;  m.z = (j + 2 < len) ? 1.f : 0.f;
            o.w = (j + 3 < len) ? lrow[j + 3] : 0.f;  m.w = (j + 3 < len) ? 1.f : 0.f;
            __stcs(&orow[v], o);
            if (mrow) __stcs(&mrow[v], m);
        }
    }
}

// Scalar fallback for L not divisible by 4.
__global__ void logit_sep_scalar(const float* __restrict__ logits,
                                 float* __restrict__ out,
                                 float* __restrict__ mout,
                                 int D, int L) {
    const int row = blockIdx.x;
    const int b = row / D;
    const int start = g_start[row];
    const int len   = g_len[row];
    const size_t base = (size_t)row * (size_t)L;
    const float* __restrict__ lrow = logits + (size_t)b * L + start;

    for (int j = threadIdx.x; j < L; j += blockDim.x) {
        const bool in = (j < len);
        out[base + j] = in ? lrow[j] : 0.f;
        if (mout) mout[base + j] = in ? 1.f : 0.f;
    }
}

extern "C" void kernel_launch(void* const* d_in, const int* in_sizes, int n_in,
                              void* d_out, int out_size) {
    const void*  schemas = d_in[0];               // (B, D) int32 or int64
    const float* logits  = (const float*)d_in[1]; // (B, L) float32
    float* out = (float*)d_out;

    const long long S0 = in_sizes[0];  // B*D
    const long long S1 = in_sizes[1];  // B*L
    const long long OS = out_size;

    // Derive B assuming out = concat(out, mask): OS = 2*B*D*L = 2*S0*S1/B
    long long B = 0;
    int halves = 2;
    if (OS > 0 && (2 * S0 * S1) % OS == 0) {
        long long Bc = (2 * S0 * S1) / OS;
        if (Bc > 0 && S0 % Bc == 0 && S1 % Bc == 0) B = Bc;
    }
    if (B == 0 && OS > 0 && (S0 * S1) % OS == 0) {   // single-output fallback
        long long Bc = (S0 * S1) / OS;
        if (Bc > 0 && S0 % Bc == 0 && S1 % Bc == 0) { B = Bc; halves = 1; }
    }
    if (B == 0) { B = 64; }  // dataset default
    const int D = (int)(S0 / B);
    const int L = (int)(S1 / B);
    const int rows = (int)(B * D);

    float* mout = (halves == 2) ? out + (size_t)rows * L : nullptr;

    setup_rows<<<1, 128>>>(schemas, (int)B, D, L, (int)S0);

    const int threads = 256;
    if ((L & 3) == 0) {
        logit_sep_vec4<<<rows, threads>>>(logits, out, mout, D, L);
    } else {
        logit_sep_scalar<<<rows, threads>>>(logits, out, mout, D, L);
    }
}

// round 11
// speedup vs baseline: 1.2377x; 1.2377x over previous
#include <cuda_runtime.h>
#include <cuda_bf16.h>
#include <cstdint>

// LogitSeparator, fused single-kernel version.
// For each (b,d) row: out[row, 0:len] = logits[b, start:start+len], rest 0;
// mask[row, 0:len] = 1.0, rest 0. start = exclusive cumsum of schemas[b,:].
// Output buffer = concat(out, mask) as float32.
//
// Schemas dtype: reference says int64 but JAX x64-disabled emits int32.
// Detect on-device using row 0's odd 32-bit words (all-zero <=> true int64).
// Indices checked are < 2*D <= B*D words, so the probe is in-bounds under
// BOTH dtype interpretations (no OOB when the buffer is really int32).

__global__ void __launch_bounds__(256)
logit_sep_fused(const void* __restrict__ schemas_raw,
                const float* __restrict__ logits,
                float* __restrict__ out,
                float* __restrict__ mout,   // may be null
                int D, int L) {
    const int row = blockIdx.x;          // b*D + d
    const int b = row / D;
    const int d = row - b * D;

    __shared__ int s_start, s_len;

    const int lane = threadIdx.x & 31;
    if (threadIdx.x < 32) {
        // --- dtype detection (row 0 odd words; consistent across blocks) ---
        const int* w = (const int*)schemas_raw;
        int probe = 0;
        if (D <= 32) {
            if (lane < D) probe = w[2 * lane + 1];
        } else {
            for (int i = lane; i < D; i += 32) probe |= w[2 * i + 1];
        }
        const bool is64 = (__ballot_sync(0xFFFFFFFFu, probe != 0) == 0u);

        const long long* s64 = (const long long*)schemas_raw;
        const int*       s32 = (const int*)schemas_raw;

        long long start = 0, len = 0;
        if (D <= 32) {
            long long v = 0;
            if (lane < D)
                v = is64 ? s64[(long long)b * D + lane]
                         : (long long)s32[(long long)b * D + lane];
            long long incl = v;
            #pragma unroll
            for (int o = 1; o < 32; o <<= 1) {
                long long t = __shfl_up_sync(0xFFFFFFFFu, incl, o);
                if (lane >= o) incl += t;
            }
            // lane d holds this row's inclusive sum and its own value
            start = __shfl_sync(0xFFFFFFFFu, incl - v, d);
            len   = __shfl_sync(0xFFFFFFFFu, v, d);
        } else if (lane == 0) {
            long long cum = 0;
            for (int i = 0; i < d; ++i)
                cum += is64 ? s64[(long long)b * D + i]
                            : (long long)s32[(long long)b * D + i];
            start = cum;
            len = is64 ? s64[(long long)b * D + d]
                       : (long long)s32[(long long)b * D + d];
        }
        if (lane == 0) {
            // clamp zone to [0, L)
            long long zs = start < L ? start : L;
            long long ze = start + len; ze = ze < L ? ze : L;
            long long le = ze - zs; if (le < 0) le = 0;
            s_start = (int)zs;
            s_len   = (int)le;
        }
    }
    __syncthreads();

    const int start = s_start;
    const int len   = s_len;

    const size_t base = (size_t)row * (size_t)L;
    float4* __restrict__ orow = (float4*)(out + base);
    float4* __restrict__ mrow = mout ? (float4*)(mout + base) : nullptr;
    const float* __restrict__ lrow = logits + (size_t)b * L + start;

    const int nvec = L >> 2;
    const float4 z4   = make_float4(0.f, 0.f, 0.f, 0.f);
    const float4 one4 = make_float4(1.f, 1.f, 1.f, 1.f);

    for (int v = threadIdx.x; v < nvec; v += blockDim.x) {
        const int j = v << 2;
        if (j >= len) {
            // dominant path: streaming zero stores
            __stcs(&orow[v], z4);
            if (mrow) __stcs(&mrow[v], z4);
        } else if (j + 3 < len) {
            float4 o = make_float4(lrow[j], lrow[j + 1], lrow[j + 2], lrow[j + 3]);
            __stcs(&orow[v], o);
            if (mrow) __stcs(&mrow[v], one4);
        } else {
            // boundary vector (at most one per row)
            float4 o, m;
            o.x = (j + 0 < len) ? lrow[j + 0] : 0.f;  m.x = (j + 0 < len) ? 1.f : 0.f;
            o.y = (j + 1 < len) ? lrow[j + 1] : 0.f;  m.y = (j + 1 < len) ? 1.f : 0.f;
            o.z = (j + 2 < len) ? lrow[j + 2] : 0.f;  m.z = (j + 2 < len) ? 1.f : 0.f;
            o.w = (j + 3 < len) ? lrow[j + 3] : 0.f;  m.w = (j + 3 < len) ? 1.f : 0.f;
            __stcs(&orow[v], o);
            if (mrow) __stcs(&mrow[v], m);
        }
    }
}

// Scalar fallback for L not divisible by 4 (same fused scheme, scalar stores).
__global__ void logit_sep_fused_scalar(const void* __restrict__ schemas_raw,
                                       const float* __restrict__ logits,
                                       float* __restrict__ out,
                                       float* __restrict__ mout,
                                       int D, int L) {
    const int row = blockIdx.x;
    const int b = row / D;
    const int d = row - b * D;

    __shared__ int s_start, s_len;
    if (threadIdx.x == 0) {
        const int* w = (const int*)schemas_raw;
        int any = 0;
        for (int i = 0; i < D; ++i) any |= w[2 * i + 1];
        const bool is64 = (any == 0);
        const long long* s64 = (const long long*)schemas_raw;
        const int*       s32 = (const int*)schemas_raw;
        long long cum = 0;
        for (int i = 0; i < d; ++i)
            cum += is64 ? s64[(long long)b * D + i] : (long long)s32[(long long)b * D + i];
        long long v = is64 ? s64[(long long)b * D + d] : (long long)s32[(long long)b * D + d];
        long long zs = cum < L ? cum : L;
        long long ze = cum + v; ze = ze < L ? ze : L;
        long long le = ze - zs; if (le < 0) le = 0;
        s_start = (int)zs;
        s_len   = (int)le;
    }
    __syncthreads();

    const int start = s_start;
    const int len   = s_len;
    const size_t base = (size_t)row * (size_t)L;
    const float* __restrict__ lrow = logits + (size_t)b * L + start;

    for (int j = threadIdx.x; j < L; j += blockDim.x) {
        const bool in = (j < len);
        out[base + j] = in ? lrow[j] : 0.f;
        if (mout) mout[base + j] = in ? 1.f : 0.f;
    }
}

extern "C" void kernel_launch(void* const* d_in, const int* in_sizes, int n_in,
                              void* d_out, int out_size) {
    const void*  schemas = d_in[0];               // (B, D) int32 or int64
    const float* logits  = (const float*)d_in[1]; // (B, L) float32
    float* out = (float*)d_out;

    const long long S0 = in_sizes[0];  // B*D
    const long long S1 = in_sizes[1];  // B*L
    const long long OS = out_size;

    // Derive B assuming out = concat(out, mask): OS = 2*B*D*L = 2*S0*S1/B
    long long B = 0;
    int halves = 2;
    if (OS > 0 && (2 * S0 * S1) % OS == 0) {
        long long Bc = (2 * S0 * S1) / OS;
        if (Bc > 0 && S0 % Bc == 0 && S1 % Bc == 0) B = Bc;
    }
    if (B == 0 && OS > 0 && (S0 * S1) % OS == 0) {   // single-output fallback
        long long Bc = (S0 * S1) / OS;
        if (Bc > 0 && S0 % Bc == 0 && S1 % Bc == 0) { B = Bc; halves = 1; }
    }
    if (B == 0) { B = 64; }  // dataset default
    const int D = (int)(S0 / B);
    const int L = (int)(S1 / B);
    const int rows = (int)(B * D);

    float* mout = (halves == 2) ? out + (size_t)rows * L : nullptr;

    const int threads = 256;
    if ((L & 3) == 0) {
        logit_sep_fused<<<rows, threads>>>(schemas, logits, out, mout, D, L);
    } else {
        logit_sep_fused_scalar<<<rows, threads>>>(schemas, logits, out, mout, D, L);
    }
}